// round 9
// baseline (speedup 1.0000x reference)
#include <cuda_runtime.h>
#include <cuda_bf16.h>
#include <math.h>
#include <stdint.h>

// ---------------------------------------------------------------------------
// Problem constants
// ---------------------------------------------------------------------------
#define BWIN   4096
#define NTOK   49
#define CDIM   384
#define NHEAD  12
#define HD     32
#define NWMASK 64
#define TOKENS (BWIN * NTOK)   // 200704
#define QKV_COLS (3 * CDIM)    // 1152
#define NN (NTOK * NTOK)       // 2401

// Scratch
__device__ float g_q[(size_t)BWIN * NHEAD * NTOK * HD];
__device__ float g_k[(size_t)BWIN * NHEAD * NTOK * HD];
__device__ float g_v[(size_t)BWIN * NHEAD * NTOK * HD];
__device__ float g_ctx[(size_t)TOKENS * CDIM];
__device__ float g_mb[(size_t)NWMASK * NHEAD * NN];

// ---------------------------------------------------------------------------
// helpers
// ---------------------------------------------------------------------------
__device__ __forceinline__ uint32_t smem_to_u32(const void* smem_ptr) {
    uint32_t addr;
    asm("{ .reg .u64 tmp; cvta.to.shared.u64 tmp, %1; cvt.u32.u64 %0, tmp; }"
        : "=r"(addr) : "l"(smem_ptr));
    return addr;
}

__device__ __forceinline__ void ldsm4(uint32_t r[4], uint32_t addr) {
    asm volatile("ldmatrix.sync.aligned.m8n8.x4.shared.b16 {%0,%1,%2,%3}, [%4];"
        : "=r"(r[0]), "=r"(r[1]), "=r"(r[2]), "=r"(r[3]) : "r"(addr));
}

__device__ __forceinline__ void mma_bf16(float c[4], const uint32_t a[4],
                                         uint32_t b0, uint32_t b1) {
    asm volatile(
        "mma.sync.aligned.m16n8k16.row.col.f32.bf16.bf16.f32 "
        "{%0,%1,%2,%3}, {%4,%5,%6,%7}, {%8,%9}, {%0,%1,%2,%3};"
        : "+f"(c[0]), "+f"(c[1]), "+f"(c[2]), "+f"(c[3])
        : "r"(a[0]), "r"(a[1]), "r"(a[2]), "r"(a[3]), "r"(b0), "r"(b1));
}

// split fp32x4 into hi/lo bf16x4, store 8B each
__device__ __forceinline__ void split_sts(float4 a, uint32_t hi_addr, uint32_t lo_addr)
{
    __nv_bfloat16 h0 = __float2bfloat16(a.x);
    __nv_bfloat16 h1 = __float2bfloat16(a.y);
    __nv_bfloat16 h2 = __float2bfloat16(a.z);
    __nv_bfloat16 h3 = __float2bfloat16(a.w);
    __nv_bfloat16 l0 = __float2bfloat16(a.x - __bfloat162float(h0));
    __nv_bfloat16 l1 = __float2bfloat16(a.y - __bfloat162float(h1));
    __nv_bfloat16 l2 = __float2bfloat16(a.z - __bfloat162float(h2));
    __nv_bfloat16 l3 = __float2bfloat16(a.w - __bfloat162float(h3));
    uint32_t hx = (uint32_t)__bfloat16_as_ushort(h0) | ((uint32_t)__bfloat16_as_ushort(h1) << 16);
    uint32_t hy = (uint32_t)__bfloat16_as_ushort(h2) | ((uint32_t)__bfloat16_as_ushort(h3) << 16);
    uint32_t lx = (uint32_t)__bfloat16_as_ushort(l0) | ((uint32_t)__bfloat16_as_ushort(l1) << 16);
    uint32_t ly = (uint32_t)__bfloat16_as_ushort(l2) | ((uint32_t)__bfloat16_as_ushort(l3) << 16);
    asm volatile("st.shared.v2.u32 [%0], {%1, %2};" :: "r"(hi_addr), "r"(hx), "r"(hy) : "memory");
    asm volatile("st.shared.v2.u32 [%0], {%1, %2};" :: "r"(lo_addr), "r"(lx), "r"(ly) : "memory");
}

// ---------------------------------------------------------------------------
// GEMM — EXACT R7 implementation (proven: gemm0 1.83ms, gemm1 0.61ms)
// 128x64 tile, K chunks of 32, double-buffered, ldmatrix, split-bf16 HMMA.
// ---------------------------------------------------------------------------
#define TM 128
#define TN 64
#define KCH 32
#define NCH (CDIM / KCH)            // 12
#define ROWSTR 40
#define A_HALF (TM * ROWSTR * 2)    // 10240
#define B_HALF (TN * ROWSTR * 2)    // 5120
#define STAGE (2 * A_HALF + 2 * B_HALF)  // 30720
#define GEMM_SMEM (2 * STAGE)       // 61440

template<int MODE>
__global__ __launch_bounds__(256) void gemm_mma_kernel(
    const float* __restrict__ Ain,
    const float* __restrict__ B,
    const float* __restrict__ bias,
    float* __restrict__ Cout)
{
    // g_ctx must be resolved in DEVICE code (host shadow addr reads zeros).
    const float* __restrict__ A = (MODE == 1) ? (const float*)g_ctx : Ain;

    extern __shared__ char smem[];
    const uint32_t sb = smem_to_u32(smem);
    const int tid = threadIdx.x;
    const int wid = tid >> 5;
    const int lane = tid & 31;
    const int m0 = blockIdx.y * TM;
    const int n0 = blockIdx.x * TN;
    const int wm = wid & 1;
    const int wn = wid >> 1;
    const int g = lane >> 2;
    const int t = lane & 3;

    float acc[4][2][4];
#pragma unroll
    for (int i = 0; i < 4; i++)
#pragma unroll
        for (int j = 0; j < 2; j++)
#pragma unroll
            for (int k = 0; k < 4; k++) acc[i][j][k] = 0.f;

    float4 la[4], lb[2];

    const uint32_t aAddrBase =
        ((uint32_t)((wm * 64 + (lane & 15)) * ROWSTR + (lane >> 4) * 8)) * 2;
    const uint32_t bAddrBase =
        ((uint32_t)((wn * 16 + (lane & 7) + ((lane >> 4) & 1) * 8) * ROWSTR
                    + ((lane >> 3) & 1) * 8)) * 2;

    {
#pragma unroll
        for (int i = 0; i < 4; i++) {
            const int v = tid + 256 * i;
            la[i] = *(const float4*)&A[(size_t)(m0 + (v >> 3)) * CDIM + (v & 7) * 4];
        }
#pragma unroll
        for (int i = 0; i < 2; i++) {
            const int v = tid + 256 * i;
            lb[i] = *(const float4*)&B[(size_t)(n0 + (v >> 3)) * CDIM + (v & 7) * 4];
        }
#pragma unroll
        for (int i = 0; i < 4; i++) {
            const int v = tid + 256 * i;
            const uint32_t off = (uint32_t)((v >> 3) * ROWSTR + (v & 7) * 4) * 2;
            split_sts(la[i], sb + off, sb + A_HALF + off);
        }
#pragma unroll
        for (int i = 0; i < 2; i++) {
            const int v = tid + 256 * i;
            const uint32_t off = (uint32_t)((v >> 3) * ROWSTR + (v & 7) * 4) * 2;
            split_sts(lb[i], sb + 2 * A_HALF + off, sb + 2 * A_HALF + B_HALF + off);
        }
    }
    __syncthreads();

    for (int c = 0; c < NCH; c++) {
        if (c + 1 < NCH) {
            const int k0 = (c + 1) * KCH;
#pragma unroll
            for (int i = 0; i < 4; i++) {
                const int v = tid + 256 * i;
                la[i] = *(const float4*)&A[(size_t)(m0 + (v >> 3)) * CDIM + k0 + (v & 7) * 4];
            }
#pragma unroll
            for (int i = 0; i < 2; i++) {
                const int v = tid + 256 * i;
                lb[i] = *(const float4*)&B[(size_t)(n0 + (v >> 3)) * CDIM + k0 + (v & 7) * 4];
            }
        }
        {
            const uint32_t stb = sb + (uint32_t)(c & 1) * STAGE;
#pragma unroll
            for (int kk = 0; kk < 2; kk++) {
                uint32_t bh[4], bl[4];
                const uint32_t baddr = stb + 2 * A_HALF + bAddrBase + kk * 32;
                ldsm4(bh, baddr);
                ldsm4(bl, baddr + B_HALF);
#pragma unroll
                for (int mf = 0; mf < 4; mf++) {
                    uint32_t ah[4], al[4];
                    const uint32_t aaddr = stb + aAddrBase
                        + (uint32_t)(mf * 16 * ROWSTR + kk * 16) * 2;
                    ldsm4(ah, aaddr);
                    ldsm4(al, aaddr + A_HALF);
#pragma unroll
                    for (int nf = 0; nf < 2; nf++) {
                        mma_bf16(acc[mf][nf], ah, bh[nf * 2], bh[nf * 2 + 1]);
                        mma_bf16(acc[mf][nf], ah, bl[nf * 2], bl[nf * 2 + 1]);
                        mma_bf16(acc[mf][nf], al, bh[nf * 2], bh[nf * 2 + 1]);
                    }
                }
            }
        }
        if (c + 1 < NCH) {
            const uint32_t base = sb + (uint32_t)((c + 1) & 1) * STAGE;
#pragma unroll
            for (int i = 0; i < 4; i++) {
                const int v = tid + 256 * i;
                const uint32_t off = (uint32_t)((v >> 3) * ROWSTR + (v & 7) * 4) * 2;
                split_sts(la[i], base + off, base + A_HALF + off);
            }
#pragma unroll
            for (int i = 0; i < 2; i++) {
                const int v = tid + 256 * i;
                const uint32_t off = (uint32_t)((v >> 3) * ROWSTR + (v & 7) * 4) * 2;
                split_sts(lb[i], base + 2 * A_HALF + off, base + 2 * A_HALF + B_HALF + off);
            }
        }
        __syncthreads();
    }

    const int rbase = m0 + wm * 64;
    const int colw = n0 + wn * 16;

#pragma unroll
    for (int mf = 0; mf < 4; mf++) {
#pragma unroll
        for (int nf = 0; nf < 2; nf++) {
            const int col = colw + nf * 8 + 2 * t;
            const float2 bs = *(const float2*)&bias[col];
            if (MODE == 0) {
                const int three = n0 / CDIM;
                const int colseg = col - three * CDIM;
                const int h = colseg >> 5;
                const int d = colseg & 31;
                float* __restrict__ dst = (three == 0) ? g_q : ((three == 1) ? g_k : g_v);
                const float sc = (three == 0) ? 0.17677669529663687f : 1.0f;
#pragma unroll
                for (int hf = 0; hf < 2; hf++) {
                    const int r = rbase + mf * 16 + g + hf * 8;
                    const int bw = r / NTOK;
                    const int n = r - bw * NTOK;
                    float2 o;
                    o.x = (acc[mf][nf][hf * 2 + 0] + bs.x) * sc;
                    o.y = (acc[mf][nf][hf * 2 + 1] + bs.y) * sc;
                    *(float2*)&dst[(((size_t)bw * NHEAD + h) * NTOK + n) * HD + d] = o;
                }
            } else {
#pragma unroll
                for (int hf = 0; hf < 2; hf++) {
                    const int r = rbase + mf * 16 + g + hf * 8;
                    float2 o;
                    o.x = acc[mf][nf][hf * 2 + 0] + bs.x;
                    o.y = acc[mf][nf][hf * 2 + 1] + bs.y;
                    *(float2*)&Cout[(size_t)r * CDIM + col] = o;
                }
            }
        }
    }
}

// ---------------------------------------------------------------------------
// Prep: g_mb[w][h][i*49+j] = mask[w][i][j] + bias_table[rel_index[i][j]][h]
// ---------------------------------------------------------------------------
__global__ __launch_bounds__(256) void prep_mb_kernel(
    const float* __restrict__ mask,
    const float* __restrict__ bias_table,
    const int*   __restrict__ rel_index)
{
    const int idx = blockIdx.x * 256 + threadIdx.x;
    if (idx >= NWMASK * NHEAD * NN) return;
    const int ij = idx % NN;
    const int wh = idx / NN;
    const int h = wh % NHEAD;
    const int w = wh / NHEAD;
    g_mb[idx] = mask[(size_t)w * NN + ij] + bias_table[rel_index[ij] * NHEAD + h];
}

// ---------------------------------------------------------------------------
// Attention (R8 version, ctx out as f32): transposed smem, float4 reads.
// ---------------------------------------------------------------------------
#define QW 52
#define KW 68
#define VW 52
#define SW 52

__global__ __launch_bounds__(256) void attn_kernel(void)
{
    const int bh = blockIdx.x;
    const int b = bh / NHEAD;
    const int h = bh - b * NHEAD;
    const int wmask = b & (NWMASK - 1);

    __shared__ float qsT[HD * QW];     // [d][n]
    __shared__ float ksT[HD * KW];     // [d][n]
    __shared__ float vsT[HD * VW];     // [d][n], cols 49..51 zeroed
    __shared__ float s[52 * SW];       // [i][j], cols 49..51 zeroed

    const float* __restrict__ qg = g_q + (size_t)bh * NTOK * HD;
    const float* __restrict__ kg = g_k + (size_t)bh * NTOK * HD;
    const float* __restrict__ vg = g_v + (size_t)bh * NTOK * HD;
    const float* __restrict__ mb = g_mb + (size_t)(wmask * NHEAD + h) * NN;

    const int tid = threadIdx.x;
    if (tid < 96)  vsT[(tid / 3) * VW + 49 + (tid % 3)] = 0.f;
    if (tid < 156) s[(tid / 3) * SW + 49 + (tid % 3)] = 0.f;

    for (int idx = tid; idx < NTOK * HD; idx += 256) {
        const int n = idx >> 5;
        const int d = idx & 31;
        qsT[d * QW + n] = qg[idx];
        ksT[d * KW + n] = kg[idx];
        vsT[d * VW + n] = vg[idx];
    }
    __syncthreads();

    const int warp = tid >> 5;
    const int lane = tid & 31;
    const int j1ok = (lane < NTOK - 32);

    // ---- scores: 13 i-tiles of 4 rows; lane = j ----
    for (int it = warp; it < 13; it += 8) {
        const int i0 = it * 4;
        float a0[4] = {0.f, 0.f, 0.f, 0.f};
        float a1[4] = {0.f, 0.f, 0.f, 0.f};
#pragma unroll
        for (int m = 0; m < HD; m++) {
            const float4 qv = *(const float4*)&qsT[m * QW + i0];   // broadcast
            const float kv0 = ksT[m * KW + lane];
            const float kv1 = ksT[m * KW + lane + 32];             // garbage if !j1ok
            a0[0] += qv.x * kv0; a0[1] += qv.y * kv0;
            a0[2] += qv.z * kv0; a0[3] += qv.w * kv0;
            a1[0] += qv.x * kv1; a1[1] += qv.y * kv1;
            a1[2] += qv.z * kv1; a1[3] += qv.w * kv1;
        }
#pragma unroll
        for (int r = 0; r < 4; r++) {
            const int i = i0 + r;
            if (i < NTOK) {
                s[i * SW + lane] = a0[r] + mb[i * NTOK + lane];
                if (j1ok) s[i * SW + lane + 32] = a1[r] + mb[i * NTOK + lane + 32];
            }
        }
    }
    __syncthreads();

    // ---- softmax: one warp per row ----
    for (int i = warp; i < NTOK; i += 8) {
        float v0 = s[i * SW + lane];
        float v1 = j1ok ? s[i * SW + lane + 32] : -INFINITY;
        float mx = fmaxf(v0, v1);
#pragma unroll
        for (int o = 16; o > 0; o >>= 1)
            mx = fmaxf(mx, __shfl_xor_sync(0xFFFFFFFFu, mx, o));
        float e0 = __expf(v0 - mx);
        float e1 = j1ok ? __expf(v1 - mx) : 0.f;
        float sum = e0 + e1;
#pragma unroll
        for (int o = 16; o > 0; o >>= 1)
            sum += __shfl_xor_sync(0xFFFFFFFFu, sum, o);
        const float inv = 1.f / sum;
        s[i * SW + lane] = e0 * inv;
        if (j1ok) s[i * SW + lane + 32] = e1 * inv;
    }
    __syncthreads();

    // ---- AV: 13 i-tiles of 4 rows; lane = d ----
    float* __restrict__ cg = g_ctx + ((size_t)b * NTOK) * CDIM + h * HD;
    for (int it = warp; it < 13; it += 8) {
        const int i0 = it * 4;
        float a[4] = {0.f, 0.f, 0.f, 0.f};
#pragma unroll
        for (int j4 = 0; j4 < 13; j4++) {
            const float4 vv = *(const float4*)&vsT[lane * VW + j4 * 4];
#pragma unroll
            for (int r = 0; r < 4; r++) {
                const float4 s4 = *(const float4*)&s[(i0 + r) * SW + j4 * 4];  // broadcast
                a[r] += s4.x * vv.x + s4.y * vv.y + s4.z * vv.z + s4.w * vv.w;
            }
        }
#pragma unroll
        for (int r = 0; r < 4; r++) {
            const int i = i0 + r;
            if (i < NTOK) cg[(size_t)i * CDIM + lane] = a[r];
        }
    }
}

// ---------------------------------------------------------------------------
// launch
// ---------------------------------------------------------------------------
extern "C" void kernel_launch(void* const* d_in, const int* in_sizes, int n_in,
                              void* d_out, int out_size)
{
    const float* x          = (const float*)d_in[0];
    const float* mask       = (const float*)d_in[1];
    const float* qkv_w      = (const float*)d_in[2];
    const float* qkv_b      = (const float*)d_in[3];
    const float* proj_w     = (const float*)d_in[4];
    const float* proj_b     = (const float*)d_in[5];
    const float* bias_table = (const float*)d_in[6];
    const int*   rel_index  = (const int*)d_in[7];
    float* out = (float*)d_out;

    cudaFuncSetAttribute(gemm_mma_kernel<0>, cudaFuncAttributeMaxDynamicSharedMemorySize, GEMM_SMEM);
    cudaFuncSetAttribute(gemm_mma_kernel<1>, cudaFuncAttributeMaxDynamicSharedMemorySize, GEMM_SMEM);

    prep_mb_kernel<<<(NWMASK * NHEAD * NN + 255) / 256, 256>>>(mask, bias_table, rel_index);

    // QKV: A = x [TOKENS,384], B = qkv_w [1152,384]
    dim3 g1(QKV_COLS / TN, TOKENS / TM);   // (18, 1568)
    gemm_mma_kernel<0><<<g1, 256, GEMM_SMEM>>>(x, qkv_w, qkv_b, nullptr);

    attn_kernel<<<BWIN * NHEAD, 256>>>();

    // Proj: A = g_ctx (resolved inside the kernel), B = proj_w [384,384]
    dim3 g2(CDIM / TN, TOKENS / TM);       // (6, 1568)
    gemm_mma_kernel<1><<<g2, 256, GEMM_SMEM>>>(nullptr, proj_w, proj_b, out);
}

// round 10
// speedup vs baseline: 1.2112x; 1.2112x over previous
#include <cuda_runtime.h>
#include <cuda_bf16.h>
#include <math.h>
#include <stdint.h>

// ---------------------------------------------------------------------------
// Problem constants
// ---------------------------------------------------------------------------
#define BWIN   4096
#define NTOK   49
#define CDIM   384
#define NHEAD  12
#define HD     32
#define NWMASK 64
#define TOKENS (BWIN * NTOK)   // 200704
#define QKV_COLS (3 * CDIM)    // 1152
#define NN (NTOK * NTOK)       // 2401

// Scratch (device globals; referenced ONLY from device code)
__device__ float g_q[(size_t)BWIN * NHEAD * NTOK * HD];
__device__ float g_k[(size_t)BWIN * NHEAD * NTOK * HD];
__device__ float g_v[(size_t)BWIN * NHEAD * NTOK * HD];
__device__ float g_mb[(size_t)NWMASK * NHEAD * NN];
__device__ __nv_bfloat16 g_xh[(size_t)TOKENS * CDIM];
__device__ __nv_bfloat16 g_xl[(size_t)TOKENS * CDIM];
__device__ __nv_bfloat16 g_wqh[(size_t)QKV_COLS * CDIM];
__device__ __nv_bfloat16 g_wql[(size_t)QKV_COLS * CDIM];
__device__ __nv_bfloat16 g_wph[(size_t)CDIM * CDIM];
__device__ __nv_bfloat16 g_wpl[(size_t)CDIM * CDIM];
__device__ __nv_bfloat16 g_ctxh[(size_t)TOKENS * CDIM];
__device__ __nv_bfloat16 g_ctxl[(size_t)TOKENS * CDIM];

// ---------------------------------------------------------------------------
// helpers
// ---------------------------------------------------------------------------
__device__ __forceinline__ uint32_t smem_to_u32(const void* smem_ptr) {
    uint32_t addr;
    asm("{ .reg .u64 tmp; cvta.to.shared.u64 tmp, %1; cvt.u32.u64 %0, tmp; }"
        : "=r"(addr) : "l"(smem_ptr));
    return addr;
}

__device__ __forceinline__ void ldsm4(uint32_t r[4], uint32_t addr) {
    asm volatile("ldmatrix.sync.aligned.m8n8.x4.shared.b16 {%0,%1,%2,%3}, [%4];"
        : "=r"(r[0]), "=r"(r[1]), "=r"(r[2]), "=r"(r[3]) : "r"(addr));
}

__device__ __forceinline__ void mma_bf16(float c[4], const uint32_t a[4],
                                         uint32_t b0, uint32_t b1) {
    asm volatile(
        "mma.sync.aligned.m16n8k16.row.col.f32.bf16.bf16.f32 "
        "{%0,%1,%2,%3}, {%4,%5,%6,%7}, {%8,%9}, {%0,%1,%2,%3};"
        : "+f"(c[0]), "+f"(c[1]), "+f"(c[2]), "+f"(c[3])
        : "r"(a[0]), "r"(a[1]), "r"(a[2]), "r"(a[3]), "r"(b0), "r"(b1));
}

#define CP_ASYNC_16(dst, src) \
    asm volatile("cp.async.ca.shared.global [%0], [%1], 16;" \
        :: "r"(dst), "l"(src) : "memory")
#define CP_COMMIT() asm volatile("cp.async.commit_group;" ::: "memory")
#define CP_WAIT1()  asm volatile("cp.async.wait_group 1;" ::: "memory")
#define CP_WAIT0()  asm volatile("cp.async.wait_group 0;" ::: "memory")

// ---------------------------------------------------------------------------
// Prep: split fp32 arrays into bf16 hi/lo
// ---------------------------------------------------------------------------
template<int WHICH>
__global__ __launch_bounds__(256) void split_kernel(const float* __restrict__ src)
{
    const size_t count = (WHICH == 0) ? (size_t)TOKENS * CDIM
                       : (WHICH == 1) ? (size_t)QKV_COLS * CDIM
                                      : (size_t)CDIM * CDIM;
    __nv_bfloat16* __restrict__ dh = (WHICH == 0) ? g_xh : (WHICH == 1) ? g_wqh : g_wph;
    __nv_bfloat16* __restrict__ dl = (WHICH == 0) ? g_xl : (WHICH == 1) ? g_wql : g_wpl;

    const size_t i4 = (size_t)blockIdx.x * 256 + threadIdx.x;
    if (i4 * 4 >= count) return;
    float4 a = *(const float4*)&src[i4 * 4];
    __nv_bfloat16 h0 = __float2bfloat16(a.x), h1 = __float2bfloat16(a.y);
    __nv_bfloat16 h2 = __float2bfloat16(a.z), h3 = __float2bfloat16(a.w);
    __nv_bfloat16 l0 = __float2bfloat16(a.x - __bfloat162float(h0));
    __nv_bfloat16 l1 = __float2bfloat16(a.y - __bfloat162float(h1));
    __nv_bfloat16 l2 = __float2bfloat16(a.z - __bfloat162float(h2));
    __nv_bfloat16 l3 = __float2bfloat16(a.w - __bfloat162float(h3));
    uint2 hp, lp;
    hp.x = (uint32_t)__bfloat16_as_ushort(h0) | ((uint32_t)__bfloat16_as_ushort(h1) << 16);
    hp.y = (uint32_t)__bfloat16_as_ushort(h2) | ((uint32_t)__bfloat16_as_ushort(h3) << 16);
    lp.x = (uint32_t)__bfloat16_as_ushort(l0) | ((uint32_t)__bfloat16_as_ushort(l1) << 16);
    lp.y = (uint32_t)__bfloat16_as_ushort(l2) | ((uint32_t)__bfloat16_as_ushort(l3) << 16);
    *(uint2*)&dh[i4 * 4] = hp;
    *(uint2*)&dl[i4 * 4] = lp;
}

// ---------------------------------------------------------------------------
// Prep: g_mb[w][h][i*49+j] = mask[w][i][j] + bias_table[rel_index[i][j]][h]
// ---------------------------------------------------------------------------
__global__ __launch_bounds__(256) void prep_mb_kernel(
    const float* __restrict__ mask,
    const float* __restrict__ bias_table,
    const int*   __restrict__ rel_index)
{
    const int idx = blockIdx.x * 256 + threadIdx.x;
    if (idx >= NWMASK * NHEAD * NN) return;
    const int ij = idx % NN;
    const int wh = idx / NN;
    const int h = wh % NHEAD;
    const int w = wh / NHEAD;
    g_mb[idx] = mask[(size_t)w * NN + ij] + bias_table[rel_index[ij] * NHEAD + h];
}

// ---------------------------------------------------------------------------
// GEMM (R8 version — measured faster): 128x128 tile, cp.async, pre-split bf16.
// 8 warps: wm=wid&1 (M64), wn=wid>>1 (N32). 3-term split-bf16 HMMA.
// ---------------------------------------------------------------------------
#define TM 128
#define TN 128
#define KCH 32
#define NCH (CDIM / KCH)            // 12
#define ROWSTR 40                   // bf16 per smem row (80B)
#define BUF_AH 0
#define BUF_AL 10240
#define BUF_BH 20480
#define BUF_BL 30720
#define STAGE  40960
#define GEMM_SMEM (2 * STAGE)       // 81920

// MODE 0: A=g_xh/xl, B=g_wqh/wql, scatter to g_q/g_k/g_v (+bias, q scaled)
// MODE 1: A=g_ctxh/ctxl, B=g_wph/wpl, dense out (+bias)
template<int MODE>
__global__ __launch_bounds__(256) void gemm_mma_kernel(
    const float* __restrict__ bias,
    float* __restrict__ Cout)
{
    const __nv_bfloat16* __restrict__ Ah = (MODE == 0) ? g_xh : g_ctxh;
    const __nv_bfloat16* __restrict__ Al = (MODE == 0) ? g_xl : g_ctxl;
    const __nv_bfloat16* __restrict__ Bh = (MODE == 0) ? g_wqh : g_wph;
    const __nv_bfloat16* __restrict__ Bl = (MODE == 0) ? g_wql : g_wpl;

    extern __shared__ char smem[];
    const uint32_t sb = smem_to_u32(smem);
    const int tid = threadIdx.x;
    const int wid = tid >> 5;
    const int lane = tid & 31;
    const int m0 = blockIdx.y * TM;
    const int n0 = blockIdx.x * TN;
    const int wm = wid & 1;
    const int wn = wid >> 1;
    const int g = lane >> 2;
    const int t = lane & 3;

    const int row0 = tid >> 2, jc0 = tid & 3;
    const int row1 = (tid + 256) >> 2, jc1 = tid & 3;
    const uint32_t soff0 = (uint32_t)(row0 * 80 + jc0 * 16);
    const uint32_t soff1 = (uint32_t)(row1 * 80 + jc1 * 16);

    float acc[4][4][4];
#pragma unroll
    for (int i = 0; i < 4; i++)
#pragma unroll
        for (int j = 0; j < 4; j++)
#pragma unroll
            for (int k = 0; k < 4; k++) acc[i][j][k] = 0.f;

    const uint32_t aAddrBase =
        ((uint32_t)((wm * 64 + (lane & 15)) * ROWSTR + (lane >> 4) * 8)) * 2;
    const uint32_t bAddrBase =
        ((uint32_t)((wn * 32 + (lane & 7) + ((lane >> 4) & 1) * 8) * ROWSTR
                    + ((lane >> 3) & 1) * 8)) * 2;

#define ISSUE_CHUNK(stb, k0) do { \
    const __nv_bfloat16* a0 = Ah + (size_t)(m0 + row0) * CDIM + (k0) + jc0 * 8; \
    const __nv_bfloat16* a1 = Ah + (size_t)(m0 + row1) * CDIM + (k0) + jc1 * 8; \
    CP_ASYNC_16((stb) + BUF_AH + soff0, a0); \
    CP_ASYNC_16((stb) + BUF_AH + soff1, a1); \
    const __nv_bfloat16* c0 = Al + (size_t)(m0 + row0) * CDIM + (k0) + jc0 * 8; \
    const __nv_bfloat16* c1 = Al + (size_t)(m0 + row1) * CDIM + (k0) + jc1 * 8; \
    CP_ASYNC_16((stb) + BUF_AL + soff0, c0); \
    CP_ASYNC_16((stb) + BUF_AL + soff1, c1); \
    const __nv_bfloat16* b0 = Bh + (size_t)(n0 + row0) * CDIM + (k0) + jc0 * 8; \
    const __nv_bfloat16* b1 = Bh + (size_t)(n0 + row1) * CDIM + (k0) + jc1 * 8; \
    CP_ASYNC_16((stb) + BUF_BH + soff0, b0); \
    CP_ASYNC_16((stb) + BUF_BH + soff1, b1); \
    const __nv_bfloat16* d0 = Bl + (size_t)(n0 + row0) * CDIM + (k0) + jc0 * 8; \
    const __nv_bfloat16* d1 = Bl + (size_t)(n0 + row1) * CDIM + (k0) + jc1 * 8; \
    CP_ASYNC_16((stb) + BUF_BL + soff0, d0); \
    CP_ASYNC_16((stb) + BUF_BL + soff1, d1); \
    CP_COMMIT(); \
} while (0)

    ISSUE_CHUNK(sb, 0);

    for (int c = 0; c < NCH; c++) {
        if (c + 1 < NCH) {
            ISSUE_CHUNK(sb + (uint32_t)((c + 1) & 1) * STAGE, (c + 1) * KCH);
            CP_WAIT1();
        } else {
            CP_WAIT0();
        }
        __syncthreads();

        const uint32_t stb = sb + (uint32_t)(c & 1) * STAGE;
#pragma unroll
        for (int kk = 0; kk < 2; kk++) {
            uint32_t bh[2][4], bl[2][4];
#pragma unroll
            for (int nt = 0; nt < 2; nt++) {
                const uint32_t baddr = stb + BUF_BH + bAddrBase
                    + (uint32_t)(nt * 16 * ROWSTR) * 2 + kk * 32;
                ldsm4(bh[nt], baddr);
                ldsm4(bl[nt], baddr + (BUF_BL - BUF_BH));
            }
#pragma unroll
            for (int mf = 0; mf < 4; mf++) {
                uint32_t ah[4], al[4];
                const uint32_t aaddr = stb + BUF_AH + aAddrBase
                    + (uint32_t)(mf * 16 * ROWSTR + kk * 16) * 2;
                ldsm4(ah, aaddr);
                ldsm4(al, aaddr + (BUF_AL - BUF_AH));
#pragma unroll
                for (int nt = 0; nt < 2; nt++) {
#pragma unroll
                    for (int nf = 0; nf < 2; nf++) {
                        mma_bf16(acc[mf][nt * 2 + nf], ah, bh[nt][nf * 2], bh[nt][nf * 2 + 1]);
                        mma_bf16(acc[mf][nt * 2 + nf], ah, bl[nt][nf * 2], bl[nt][nf * 2 + 1]);
                        mma_bf16(acc[mf][nt * 2 + nf], al, bh[nt][nf * 2], bh[nt][nf * 2 + 1]);
                    }
                }
            }
        }
        __syncthreads();
    }
#undef ISSUE_CHUNK

    const int rbase = m0 + wm * 64;
    const int colw = n0 + wn * 32;

#pragma unroll
    for (int mf = 0; mf < 4; mf++) {
#pragma unroll
        for (int nc = 0; nc < 4; nc++) {
            const int col = colw + nc * 8 + 2 * t;
            const float2 bs = *(const float2*)&bias[col];
            if (MODE == 0) {
                const int three = n0 / CDIM;
                const int colseg = col - three * CDIM;
                const int h = colseg >> 5;
                const int d = colseg & 31;
                float* __restrict__ dst = (three == 0) ? g_q : ((three == 1) ? g_k : g_v);
                const float sc = (three == 0) ? 0.17677669529663687f : 1.0f;
#pragma unroll
                for (int hf = 0; hf < 2; hf++) {
                    const int r = rbase + mf * 16 + g + hf * 8;
                    const int bw = r / NTOK;
                    const int n = r - bw * NTOK;
                    float2 o;
                    o.x = (acc[mf][nc][hf * 2 + 0] + bs.x) * sc;
                    o.y = (acc[mf][nc][hf * 2 + 1] + bs.y) * sc;
                    *(float2*)&dst[(((size_t)bw * NHEAD + h) * NTOK + n) * HD + d] = o;
                }
            } else {
#pragma unroll
                for (int hf = 0; hf < 2; hf++) {
                    const int r = rbase + mf * 16 + g + hf * 8;
                    float2 o;
                    o.x = acc[mf][nc][hf * 2 + 0] + bs.x;
                    o.y = acc[mf][nc][hf * 2 + 1] + bs.y;
                    *(float2*)&Cout[(size_t)r * CDIM + col] = o;
                }
            }
        }
    }
}

// ---------------------------------------------------------------------------
// Attention (R7 version — measured fastest) with bf16 hi/lo ctx output.
// Row-major smem, register-blocked 4-row i-tiles, fused mb table.
// ---------------------------------------------------------------------------
__global__ __launch_bounds__(256) void attn_kernel(void)
{
    const int bh = blockIdx.x;
    const int b = bh / NHEAD;
    const int h = bh - b * NHEAD;
    const int wmask = b & (NWMASK - 1);

    __shared__ float qs[52 * 33];   // rows 49..51 zeroed
    __shared__ float ks[NTOK * 33];
    __shared__ float vs[NTOK * 33];
    __shared__ float s[52 * 50];    // rows 49..51 zeroed

    const float* __restrict__ qg = g_q + (size_t)bh * NTOK * HD;
    const float* __restrict__ kg = g_k + (size_t)bh * NTOK * HD;
    const float* __restrict__ vg = g_v + (size_t)bh * NTOK * HD;
    const float* __restrict__ mb = g_mb + (size_t)(wmask * NHEAD + h) * NN;

    for (int idx = threadIdx.x; idx < NTOK * HD; idx += 256) {
        const int n = idx >> 5;
        const int d = idx & 31;
        qs[n * 33 + d] = qg[idx];
        ks[n * 33 + d] = kg[idx];
        vs[n * 33 + d] = vg[idx];
    }
    if (threadIdx.x < 99)  qs[49 * 33 + threadIdx.x] = 0.f;
    if (threadIdx.x < 150) s[49 * 50 + threadIdx.x] = 0.f;
    __syncthreads();

    const int warp = threadIdx.x >> 5;
    const int lane = threadIdx.x & 31;
    const int j1ok = (lane < NTOK - 32);

    // ---- scores: 13 i-tiles of 4 rows ----
    for (int it = warp; it < 13; it += 8) {
        const int i0 = it * 4;
        float a0[4] = {0.f, 0.f, 0.f, 0.f};
        float a1[4] = {0.f, 0.f, 0.f, 0.f};
#pragma unroll
        for (int m = 0; m < HD; m++) {
            const float kv0 = ks[lane * 33 + m];
            const float kv1 = j1ok ? ks[(lane + 32) * 33 + m] : 0.f;
#pragma unroll
            for (int r = 0; r < 4; r++) {
                const float qv = qs[(i0 + r) * 33 + m];   // broadcast
                a0[r] += qv * kv0;
                a1[r] += qv * kv1;
            }
        }
#pragma unroll
        for (int r = 0; r < 4; r++) {
            const int i = i0 + r;
            if (i < NTOK) {
                s[i * 50 + lane] = a0[r] + mb[i * NTOK + lane];
                if (j1ok) s[i * 50 + lane + 32] = a1[r] + mb[i * NTOK + lane + 32];
            }
        }
    }
    __syncthreads();

    // ---- softmax ----
    for (int i = warp; i < NTOK; i += 8) {
        float v0 = s[i * 50 + lane];
        float v1 = j1ok ? s[i * 50 + lane + 32] : -INFINITY;
        float mx = fmaxf(v0, v1);
#pragma unroll
        for (int o = 16; o > 0; o >>= 1)
            mx = fmaxf(mx, __shfl_xor_sync(0xFFFFFFFFu, mx, o));
        float e0 = __expf(v0 - mx);
        float e1 = j1ok ? __expf(v1 - mx) : 0.f;
        float sum = e0 + e1;
#pragma unroll
        for (int o = 16; o > 0; o >>= 1)
            sum += __shfl_xor_sync(0xFFFFFFFFu, sum, o);
        const float inv = 1.f / sum;
        s[i * 50 + lane] = e0 * inv;
        if (j1ok) s[i * 50 + lane + 32] = e1 * inv;
    }
    __syncthreads();

    // ---- AV -> bf16 hi/lo ctx ----
    __nv_bfloat16* __restrict__ ch = g_ctxh + ((size_t)b * NTOK) * CDIM + h * HD;
    __nv_bfloat16* __restrict__ cl = g_ctxl + ((size_t)b * NTOK) * CDIM + h * HD;
    for (int it = warp; it < 13; it += 8) {
        const int i0 = it * 4;
        float a[4] = {0.f, 0.f, 0.f, 0.f};
        for (int j = 0; j < NTOK; j++) {
            const float vv = vs[j * 33 + lane];
#pragma unroll
            for (int r = 0; r < 4; r++)
                a[r] += s[(i0 + r) * 50 + j] * vv;   // s broadcast
        }
#pragma unroll
        for (int r = 0; r < 4; r++) {
            const int i = i0 + r;
            if (i < NTOK) {
                const float val = a[r];
                const __nv_bfloat16 hi = __float2bfloat16(val);
                const __nv_bfloat16 lo = __float2bfloat16(val - __bfloat162float(hi));
                ch[(size_t)i * CDIM + lane] = hi;
                cl[(size_t)i * CDIM + lane] = lo;
            }
        }
    }
}

// ---------------------------------------------------------------------------
// launch
// ---------------------------------------------------------------------------
extern "C" void kernel_launch(void* const* d_in, const int* in_sizes, int n_in,
                              void* d_out, int out_size)
{
    const float* x          = (const float*)d_in[0];
    const float* mask       = (const float*)d_in[1];
    const float* qkv_w      = (const float*)d_in[2];
    const float* qkv_b      = (const float*)d_in[3];
    const float* proj_w     = (const float*)d_in[4];
    const float* proj_b     = (const float*)d_in[5];
    const float* bias_table = (const float*)d_in[6];
    const int*   rel_index  = (const int*)d_in[7];
    float* out = (float*)d_out;

    cudaFuncSetAttribute(gemm_mma_kernel<0>, cudaFuncAttributeMaxDynamicSharedMemorySize, GEMM_SMEM);
    cudaFuncSetAttribute(gemm_mma_kernel<1>, cudaFuncAttributeMaxDynamicSharedMemorySize, GEMM_SMEM);

    split_kernel<0><<<(TOKENS * CDIM / 4 + 255) / 256, 256>>>(x);
    split_kernel<1><<<(QKV_COLS * CDIM / 4 + 255) / 256, 256>>>(qkv_w);
    split_kernel<2><<<(CDIM * CDIM / 4 + 255) / 256, 256>>>(proj_w);
    prep_mb_kernel<<<(NWMASK * NHEAD * NN + 255) / 256, 256>>>(mask, bias_table, rel_index);

    // QKV GEMM
    dim3 g1(QKV_COLS / TN, TOKENS / TM);   // (9, 1568)
    gemm_mma_kernel<0><<<g1, 256, GEMM_SMEM>>>(qkv_b, nullptr);

    attn_kernel<<<BWIN * NHEAD, 256>>>();

    // Proj GEMM
    dim3 g2(CDIM / TN, TOKENS / TM);       // (3, 1568)
    gemm_mma_kernel<1><<<g2, 256, GEMM_SMEM>>>(proj_b, out);
}